// round 4
// baseline (speedup 1.0000x reference)
#include <cuda_runtime.h>

// Problem constants
#define BB 16
#define TT 2048
#define DD 128
#define KK 2048
#define NCB 8
#define MM (BB*TT)          // 32768 rows
#define ROWS 128            // rows per block
#define SAS 132             // smem row stride (floats), 132*4 % 16 == 0

#define QELEMS (BB*DD*TT)           // 4194304
#define CELEMS (BB*NCB*TT)          // 262144

// Scratch (static device allocations are allowed)
__device__ float  g_residual[MM*DD];     // 16 MB, (B*T, D) row-major
__device__ float  g_cnorm[NCB*KK];       // ||c||^2 per codeword
__device__ double g_loss;

// ---------------------------------------------------------------------------
// f32x2 packed helpers (sm_100+). Bit-identical rounding to scalar fmaf.
// ---------------------------------------------------------------------------
__device__ __forceinline__ unsigned long long dup2(float a) {
    unsigned long long r;
    asm("mov.b64 %0, {%1, %1};" : "=l"(r) : "f"(a));
    return r;
}
__device__ __forceinline__ void ffma2(unsigned long long& d,
                                      unsigned long long a,
                                      unsigned long long b) {
    asm("fma.rn.f32x2 %0, %1, %2, %0;" : "+l"(d) : "l"(a), "l"(b));
}
__device__ __forceinline__ float2 unpk2(unsigned long long v) {
    float2 f;
    asm("mov.b64 {%0, %1}, %2;" : "=f"(f.x), "=f"(f.y) : "l"(v));
    return f;
}

// ---------------------------------------------------------------------------
// init: residual[(b*T+t)*D + d] = x[b*D*T + d*T + t]; zero loss accumulator
// ---------------------------------------------------------------------------
__global__ void rvq_init_kernel(const float* __restrict__ x) {
    int i = blockIdx.x * blockDim.x + threadIdx.x;
    if (i == 0) g_loss = 0.0;
    if (i < MM * DD) {
        int m = i >> 7;          // row  (b*T+t)
        int d = i & 127;
        int b = m >> 11;
        int t = m & (TT - 1);
        g_residual[i] = x[((size_t)b * DD + d) * TT + t];
    }
}

// ---------------------------------------------------------------------------
// cnorm: one warp per codeword row (all 8 stages at once)
// ---------------------------------------------------------------------------
__global__ void rvq_cnorm_kernel(const float* __restrict__ cbs) {
    int gw   = (blockIdx.x * blockDim.x + threadIdx.x) >> 5;
    int lane = threadIdx.x & 31;
    if (gw >= NCB * KK) return;
    const float* row = cbs + (size_t)gw * DD;
    float s = 0.f;
    #pragma unroll
    for (int d = lane; d < DD; d += 32) {
        float v = row[d];
        s = fmaf(v, v, s);
    }
    #pragma unroll
    for (int o = 16; o; o >>= 1) s += __shfl_xor_sync(0xffffffffu, s, o);
    if (lane == 0) g_cnorm[gw] = s;
}

// ---------------------------------------------------------------------------
// Fused stage kernel: distance GEMM + argmin + gather + residual update +
// code write + loss accumulation. Block = 256 threads, 128 rows.
// Dynamic smem: sA[128][SAS] (residual^T) + sB[128][SAS] (codeword chunk^T)
// ---------------------------------------------------------------------------
__global__ void __launch_bounds__(256, 1)
rvq_stage_kernel(const float* __restrict__ cb,      // stage codebook (K, D)
                 float* __restrict__ codes_out,     // out + QELEMS
                 int stage) {
    extern __shared__ float smem[];
    float* sA = smem;                 // 128*SAS
    float* sB = smem + ROWS * SAS;    // 128*SAS

    const int tid  = threadIdx.x;
    const int tx   = tid & 15;        // 16 col-groups of 8
    const int ty   = tid >> 4;        // 16 row-groups of 8
    const int row0 = blockIdx.x * ROWS;

    // ---- Load A tile transposed: sA[d][m] ----
    {
        const float4* src = (const float4*)(g_residual + (size_t)row0 * DD);
        #pragma unroll
        for (int it = 0; it < 16; ++it) {
            int i  = tid + it * 256;        // 0..4095
            int m  = i & 127;
            int dq = i >> 7;                // 0..31 (float4 index within row)
            float4 v = src[m * 32 + dq];
            int sb = (dq * 4) * SAS + m;    // conflict-free STS (m consecutive in warp)
            sA[sb]           = v.x;
            sA[sb + SAS]     = v.y;
            sA[sb + 2 * SAS] = v.z;
            sA[sb + 3 * SAS] = v.w;
        }
    }

    float bestv[8];
    int   besti[8];
    #pragma unroll
    for (int r = 0; r < 8; ++r) { bestv[r] = 3.402823466e38f; besti[r] = 0; }

    const float* cn_stage = g_cnorm + stage * KK;

    for (int ch = 0; ch < KK / 128; ++ch) {
        __syncthreads();   // sB safe to overwrite
        // ---- Load B chunk transposed: sB[d][n] ----
        {
            const float4* bsrc = (const float4*)(cb + (size_t)(ch * 128) * DD);
            #pragma unroll
            for (int it = 0; it < 16; ++it) {
                int i  = tid + it * 256;
                int n  = i & 127;
                int dq = i >> 7;
                float4 v = bsrc[n * 32 + dq];
                int sb = (dq * 4) * SAS + n;
                sB[sb]           = v.x;
                sB[sb + SAS]     = v.y;
                sB[sb + 2 * SAS] = v.z;
                sB[sb + 3 * SAS] = v.w;
            }
        }
        __syncthreads();

        // ---- 128x128x128 register-tiled dot products (f32x2 packed FMA) ----
        unsigned long long acc[8][4];
        #pragma unroll
        for (int r = 0; r < 8; ++r)
            #pragma unroll
            for (int c = 0; c < 4; ++c) acc[r][c] = 0ull;

        #pragma unroll 4
        for (int k = 0; k < DD; ++k) {
            float4 a0 = *(const float4*)&sA[k * SAS + (ty << 3)];
            float4 a1 = *(const float4*)&sA[k * SAS + (ty << 3) + 4];
            ulonglong2 bq0 = *(const ulonglong2*)&sB[k * SAS + (tx << 3)];
            ulonglong2 bq1 = *(const ulonglong2*)&sB[k * SAS + (tx << 3) + 4];
            unsigned long long b0 = bq0.x, b1 = bq0.y, b2 = bq1.x, b3 = bq1.y;
            float av[8] = {a0.x, a0.y, a0.z, a0.w, a1.x, a1.y, a1.z, a1.w};
            #pragma unroll
            for (int r = 0; r < 8; ++r) {
                unsigned long long ad = dup2(av[r]);
                ffma2(acc[r][0], ad, b0);
                ffma2(acc[r][1], ad, b1);
                ffma2(acc[r][2], ad, b2);
                ffma2(acc[r][3], ad, b3);
            }
        }

        // ---- scores = cnorm - 2*dot ; running argmin (ascending n => first-min) ----
        const float4* cnp = (const float4*)(cn_stage + ch * 128 + (tx << 3));
        float4 cn0 = cnp[0], cn1 = cnp[1];
        float cna[8] = {cn0.x, cn0.y, cn0.z, cn0.w, cn1.x, cn1.y, cn1.z, cn1.w};
        int nbase = ch * 128 + (tx << 3);
        #pragma unroll
        for (int r = 0; r < 8; ++r) {
            #pragma unroll
            for (int c = 0; c < 4; ++c) {
                float2 v = unpk2(acc[r][c]);
                float dlo = fmaf(-2.f, v.x, cna[2 * c]);
                float dhi = fmaf(-2.f, v.y, cna[2 * c + 1]);
                if (dlo < bestv[r]) { bestv[r] = dlo; besti[r] = nbase + 2 * c; }
                if (dhi < bestv[r]) { bestv[r] = dhi; besti[r] = nbase + 2 * c + 1; }
            }
        }
    }

    // ---- cross-thread argmin reduce (reuse sB) ----
    __syncthreads();
    float* redv = sB;
    int*   redi = (int*)(sB + ROWS * 16);
    #pragma unroll
    for (int r = 0; r < 8; ++r) {
        int m = (ty << 3) + r;
        redv[m * 16 + tx] = bestv[r];
        redi[m * 16 + tx] = besti[r];
    }
    __syncthreads();

    __shared__ int s_bidx[ROWS];
    if (tid < ROWS) {
        float bv = 3.402823466e38f;
        int   bi = 1 << 30;
        #pragma unroll
        for (int j = 0; j < 16; ++j) {
            float v  = redv[tid * 16 + j];
            int   ix = redi[tid * 16 + j];
            if (v < bv || (v == bv && ix < bi)) { bv = v; bi = ix; }
        }
        s_bidx[tid] = bi;
        int gm = row0 + tid;
        int b  = gm >> 11;
        int t  = gm & (TT - 1);
        codes_out[(size_t)b * (NCB * TT) + (size_t)stage * TT + t] = (float)bi;
    }
    __syncthreads();

    // ---- residual update + loss: 2 threads per row (64 d each) ----
    {
        int m    = tid >> 1;
        int half = tid & 1;
        int bi   = s_bidx[m];
        const float4* crow = (const float4*)(cb + (size_t)bi * DD + half * 64);
        float* gres = g_residual + ((size_t)(row0 + m)) * DD + half * 64;
        float ss = 0.f;
        #pragma unroll
        for (int q = 0; q < 16; ++q) {
            float4 c4 = crow[q];
            int d = half * 64 + q * 4;
            float r0 = sA[(d + 0) * SAS + m] - c4.x;
            float r1 = sA[(d + 1) * SAS + m] - c4.y;
            float r2 = sA[(d + 2) * SAS + m] - c4.z;
            float r3 = sA[(d + 3) * SAS + m] - c4.w;
            ((float4*)gres)[q] = make_float4(r0, r1, r2, r3);
            ss = fmaf(r0, r0, ss);
            ss = fmaf(r1, r1, ss);
            ss = fmaf(r2, r2, ss);
            ss = fmaf(r3, r3, ss);
        }
        #pragma unroll
        for (int o = 16; o; o >>= 1) ss += __shfl_xor_sync(0xffffffffu, ss, o);
        __shared__ float s_ws[8];
        int wid = tid >> 5, lane = tid & 31;
        if (lane == 0) s_ws[wid] = ss;
        __syncthreads();
        if (tid == 0) {
            float s = 0.f;
            #pragma unroll
            for (int w = 0; w < 8; ++w) s += s_ws[w];
            atomicAdd(&g_loss, (double)s);
        }
    }
}

// ---------------------------------------------------------------------------
// finalize: total_quantized = x - residual_final (transposed back), + loss
// ---------------------------------------------------------------------------
__global__ void rvq_final_kernel(const float* __restrict__ x,
                                 float* __restrict__ out) {
    int i = blockIdx.x * blockDim.x + threadIdx.x;
    if (i < QELEMS) {
        int t = i & (TT - 1);
        int d = (i >> 11) & (DD - 1);
        int b = i >> 18;
        out[i] = x[i] - g_residual[((size_t)(b * TT + t)) * DD + d];
    }
    if (i == 0) {
        out[QELEMS + CELEMS] = (float)(g_loss / (double)(MM * DD));
    }
}

// ---------------------------------------------------------------------------
extern "C" void kernel_launch(void* const* d_in, const int* in_sizes, int n_in,
                              void* d_out, int out_size) {
    const float* x   = (const float*)d_in[0];
    const float* cbs = (const float*)d_in[1];
    // Defensive input-order check by element count
    if (n_in >= 2 && in_sizes[0] == NCB * KK * DD && in_sizes[1] == QELEMS) {
        const float* tmp = x; x = cbs; cbs = tmp;
    }
    float* out = (float*)d_out;

    const int smem_bytes = 2 * ROWS * SAS * (int)sizeof(float);  // 135168
    static bool attr_set = false;
    if (!attr_set) {
        cudaFuncSetAttribute(rvq_stage_kernel,
                             cudaFuncAttributeMaxDynamicSharedMemorySize,
                             smem_bytes);
        attr_set = true;
    }

    rvq_init_kernel<<<(MM * DD + 255) / 256, 256>>>(x);
    rvq_cnorm_kernel<<<(NCB * KK * 32 + 255) / 256, 256>>>(cbs);

    for (int s = 0; s < NCB; ++s) {
        rvq_stage_kernel<<<MM / ROWS, 256, smem_bytes>>>(
            cbs + (size_t)s * KK * DD, out + QELEMS, s);
    }

    rvq_final_kernel<<<(QELEMS + 255) / 256, 256>>>(x, out);
}

// round 5
// speedup vs baseline: 1.0926x; 1.0926x over previous
#include <cuda_runtime.h>

// Problem constants
#define BB 16
#define TT 2048
#define DD 128
#define KK 2048
#define NCB 8
#define MM (BB*TT)          // 32768 rows
#define ROWS 128            // rows per block
#define SAS 132             // smem row stride (floats), 132*4 % 16 == 0

#define QELEMS (BB*DD*TT)           // 4194304
#define CELEMS (BB*NCB*TT)          // 262144

// Scratch (static device allocations are allowed)
__device__ float  g_residual[MM*DD];     // 16 MB, (B*T, D) row-major
__device__ float  g_cnorm[NCB*KK];       // ||c||^2 per codeword
__device__ double g_loss;

// ---------------------------------------------------------------------------
// f32x2 packed helpers (sm_100+). Bit-identical rounding to scalar fmaf.
// ---------------------------------------------------------------------------
__device__ __forceinline__ unsigned long long dup2(float a) {
    unsigned long long r;
    asm("mov.b64 %0, {%1, %1};" : "=l"(r) : "f"(a));
    return r;
}
__device__ __forceinline__ void ffma2(unsigned long long& d,
                                      unsigned long long a,
                                      unsigned long long b) {
    asm("fma.rn.f32x2 %0, %1, %2, %0;" : "+l"(d) : "l"(a), "l"(b));
}
__device__ __forceinline__ float2 unpk2(unsigned long long v) {
    float2 f;
    asm("mov.b64 {%0, %1}, %2;" : "=f"(f.x), "=f"(f.y) : "l"(v));
    return f;
}

// ---------------------------------------------------------------------------
// init: residual[(b*T+t)*D + d] = x[b*D*T + d*T + t]; zero loss accumulator
// ---------------------------------------------------------------------------
__global__ void rvq_init_kernel(const float* __restrict__ x) {
    int i = blockIdx.x * blockDim.x + threadIdx.x;
    if (i == 0) g_loss = 0.0;
    if (i < MM * DD) {
        int m = i >> 7;          // row  (b*T+t)
        int d = i & 127;
        int b = m >> 11;
        int t = m & (TT - 1);
        g_residual[i] = x[((size_t)b * DD + d) * TT + t];
    }
}

// ---------------------------------------------------------------------------
// cnorm: one warp per codeword row (all 8 stages at once)
// ---------------------------------------------------------------------------
__global__ void rvq_cnorm_kernel(const float* __restrict__ cbs) {
    int gw   = (blockIdx.x * blockDim.x + threadIdx.x) >> 5;
    int lane = threadIdx.x & 31;
    if (gw >= NCB * KK) return;
    const float* row = cbs + (size_t)gw * DD;
    float s = 0.f;
    #pragma unroll
    for (int d = lane; d < DD; d += 32) {
        float v = row[d];
        s = fmaf(v, v, s);
    }
    #pragma unroll
    for (int o = 16; o; o >>= 1) s += __shfl_xor_sync(0xffffffffu, s, o);
    if (lane == 0) g_cnorm[gw] = s;
}

// ---------------------------------------------------------------------------
// Fused stage kernel: distance GEMM + argmin + gather + residual update +
// code write + loss accumulation. Block = 256 threads, 128 rows.
// Register tile: 8 rows x 8 cols per thread, STRIDED float4 groups:
//   rows = ty*4 + {0..3} and 64 + ty*4 + {0..3}
//   cols = tx*4 + {0..3} and 64 + tx*4 + {0..3}
// => every LDS.128 phase hits all 32 banks exactly once (conflict-free).
// ---------------------------------------------------------------------------
__global__ void __launch_bounds__(256, 1)
rvq_stage_kernel(const float* __restrict__ cb,      // stage codebook (K, D)
                 float* __restrict__ codes_out,     // out + QELEMS
                 int stage) {
    extern __shared__ float smem[];
    float* sA = smem;                 // 128*SAS
    float* sB = smem + ROWS * SAS;    // 128*SAS

    const int tid  = threadIdx.x;
    const int tx   = tid & 15;        // col-group id
    const int ty   = tid >> 4;        // row-group id
    const int row0 = blockIdx.x * ROWS;

    // ---- Load A tile transposed: sA[d][m] ----
    {
        const float4* src = (const float4*)(g_residual + (size_t)row0 * DD);
        #pragma unroll
        for (int it = 0; it < 16; ++it) {
            int i  = tid + it * 256;        // 0..4095
            int m  = i & 127;
            int dq = i >> 7;                // 0..31 (float4 index within row)
            float4 v = src[m * 32 + dq];
            int sb = (dq * 4) * SAS + m;    // conflict-free STS
            sA[sb]           = v.x;
            sA[sb + SAS]     = v.y;
            sA[sb + 2 * SAS] = v.z;
            sA[sb + 3 * SAS] = v.w;
        }
    }

    float bestv[8];
    int   besti[8];
    #pragma unroll
    for (int r = 0; r < 8; ++r) { bestv[r] = 3.402823466e38f; besti[r] = 0; }

    const float* cn_stage = g_cnorm + stage * KK;

    for (int ch = 0; ch < KK / 128; ++ch) {
        __syncthreads();   // sB safe to overwrite
        // ---- Load B chunk transposed: sB[d][n] ----
        {
            const float4* bsrc = (const float4*)(cb + (size_t)(ch * 128) * DD);
            #pragma unroll
            for (int it = 0; it < 16; ++it) {
                int i  = tid + it * 256;
                int n  = i & 127;
                int dq = i >> 7;
                float4 v = bsrc[n * 32 + dq];
                int sb = (dq * 4) * SAS + n;
                sB[sb]           = v.x;
                sB[sb + SAS]     = v.y;
                sB[sb + 2 * SAS] = v.z;
                sB[sb + 3 * SAS] = v.w;
            }
        }
        __syncthreads();

        // ---- 128x128x128 register-tiled dot products (f32x2 packed FMA) ----
        // acc[r][c]: c=0: cols tx*4+{0,1}; c=1: tx*4+{2,3};
        //            c=2: 64+tx*4+{0,1};  c=3: 64+tx*4+{2,3}
        unsigned long long acc[8][4];
        #pragma unroll
        for (int r = 0; r < 8; ++r)
            #pragma unroll
            for (int c = 0; c < 4; ++c) acc[r][c] = 0ull;

        #pragma unroll 8
        for (int k = 0; k < DD; ++k) {
            const float* ka = &sA[k * SAS];
            const float* kb = &sB[k * SAS];
            float4 a0 = *(const float4*)&ka[ty << 2];
            float4 a1 = *(const float4*)&ka[64 + (ty << 2)];
            ulonglong2 bq0 = *(const ulonglong2*)&kb[tx << 2];
            ulonglong2 bq1 = *(const ulonglong2*)&kb[64 + (tx << 2)];
            unsigned long long b0 = bq0.x, b1 = bq0.y, b2 = bq1.x, b3 = bq1.y;
            float av[8] = {a0.x, a0.y, a0.z, a0.w, a1.x, a1.y, a1.z, a1.w};
            #pragma unroll
            for (int r = 0; r < 8; ++r) {
                unsigned long long ad = dup2(av[r]);
                ffma2(acc[r][0], ad, b0);
                ffma2(acc[r][1], ad, b1);
                ffma2(acc[r][2], ad, b2);
                ffma2(acc[r][3], ad, b3);
            }
        }

        // ---- scores = cnorm - 2*dot ; running argmin (n ascending per c) ----
        float4 cn0 = *(const float4*)(cn_stage + ch * 128 + (tx << 2));
        float4 cn1 = *(const float4*)(cn_stage + ch * 128 + 64 + (tx << 2));
        float cna[8] = {cn0.x, cn0.y, cn0.z, cn0.w, cn1.x, cn1.y, cn1.z, cn1.w};
        #pragma unroll
        for (int r = 0; r < 8; ++r) {
            #pragma unroll
            for (int c = 0; c < 4; ++c) {
                int nb = ch * 128 + (tx << 2) + ((c >> 1) << 6) + ((c & 1) << 1);
                float2 v = unpk2(acc[r][c]);
                float dlo = fmaf(-2.f, v.x, cna[2 * (c & 1) + ((c >> 1) << 2)]);
                float dhi = fmaf(-2.f, v.y, cna[2 * (c & 1) + 1 + ((c >> 1) << 2)]);
                if (dlo < bestv[r]) { bestv[r] = dlo; besti[r] = nb; }
                if (dhi < bestv[r]) { bestv[r] = dhi; besti[r] = nb + 1; }
            }
        }
    }

    // ---- cross-thread argmin reduce (reuse sB) ----
    __syncthreads();
    float* redv = sB;
    int*   redi = (int*)(sB + ROWS * 16);
    #pragma unroll
    for (int r = 0; r < 8; ++r) {
        int m = (ty << 2) + ((r >> 2) << 6) + (r & 3);
        redv[m * 16 + tx] = bestv[r];
        redi[m * 16 + tx] = besti[r];
    }
    __syncthreads();

    __shared__ int s_bidx[ROWS];
    if (tid < ROWS) {
        float bv = 3.402823466e38f;
        int   bi = 1 << 30;
        #pragma unroll
        for (int j = 0; j < 16; ++j) {
            float v  = redv[tid * 16 + j];
            int   ix = redi[tid * 16 + j];
            if (v < bv || (v == bv && ix < bi)) { bv = v; bi = ix; }
        }
        s_bidx[tid] = bi;
        int gm = row0 + tid;
        int b  = gm >> 11;
        int t  = gm & (TT - 1);
        codes_out[(size_t)b * (NCB * TT) + (size_t)stage * TT + t] = (float)bi;
    }
    __syncthreads();

    // ---- residual update + loss: 2 threads per row (64 d each) ----
    {
        int m    = tid >> 1;
        int half = tid & 1;
        int bi   = s_bidx[m];
        const float4* crow = (const float4*)(cb + (size_t)bi * DD + half * 64);
        float* gres = g_residual + ((size_t)(row0 + m)) * DD + half * 64;
        float ss = 0.f;
        #pragma unroll
        for (int q = 0; q < 16; ++q) {
            float4 c4 = crow[q];
            int d = half * 64 + q * 4;
            float r0 = sA[(d + 0) * SAS + m] - c4.x;
            float r1 = sA[(d + 1) * SAS + m] - c4.y;
            float r2 = sA[(d + 2) * SAS + m] - c4.z;
            float r3 = sA[(d + 3) * SAS + m] - c4.w;
            ((float4*)gres)[q] = make_float4(r0, r1, r2, r3);
            ss = fmaf(r0, r0, ss);
            ss = fmaf(r1, r1, ss);
            ss = fmaf(r2, r2, ss);
            ss = fmaf(r3, r3, ss);
        }
        #pragma unroll
        for (int o = 16; o; o >>= 1) ss += __shfl_xor_sync(0xffffffffu, ss, o);
        __shared__ float s_ws[8];
        int wid = tid >> 5, lane = tid & 31;
        if (lane == 0) s_ws[wid] = ss;
        __syncthreads();
        if (tid == 0) {
            float s = 0.f;
            #pragma unroll
            for (int w = 0; w < 8; ++w) s += s_ws[w];
            atomicAdd(&g_loss, (double)s);
        }
    }
}

// ---------------------------------------------------------------------------
// finalize: total_quantized = x - residual_final (transposed back), + loss
// ---------------------------------------------------------------------------
__global__ void rvq_final_kernel(const float* __restrict__ x,
                                 float* __restrict__ out) {
    int i = blockIdx.x * blockDim.x + threadIdx.x;
    if (i < QELEMS) {
        int t = i & (TT - 1);
        int d = (i >> 11) & (DD - 1);
        int b = i >> 18;
        out[i] = x[i] - g_residual[((size_t)(b * TT + t)) * DD + d];
    }
    if (i == 0) {
        out[QELEMS + CELEMS] = (float)(g_loss / (double)(MM * DD));
    }
}

// ---------------------------------------------------------------------------
extern "C" void kernel_launch(void* const* d_in, const int* in_sizes, int n_in,
                              void* d_out, int out_size) {
    const float* x   = (const float*)d_in[0];
    const float* cbs = (const float*)d_in[1];
    // Defensive input-order check by element count
    if (n_in >= 2 && in_sizes[0] == NCB * KK * DD && in_sizes[1] == QELEMS) {
        const float* tmp = x; x = cbs; cbs = tmp;
    }
    float* out = (float*)d_out;

    const int smem_bytes = 2 * ROWS * SAS * (int)sizeof(float);  // 135168
    static bool attr_set = false;
    if (!attr_set) {
        cudaFuncSetAttribute(rvq_stage_kernel,
                             cudaFuncAttributeMaxDynamicSharedMemorySize,
                             smem_bytes);
        attr_set = true;
    }

    rvq_init_kernel<<<(MM * DD + 255) / 256, 256>>>(x);
    rvq_cnorm_kernel<<<(NCB * KK * 32 + 255) / 256, 256>>>(cbs);

    for (int s = 0; s < NCB; ++s) {
        rvq_stage_kernel<<<MM / ROWS, 256, smem_bytes>>>(
            cbs + (size_t)s * KK * DD, out + QELEMS, s);
    }

    rvq_final_kernel<<<(QELEMS + 255) / 256, 256>>>(x, out);
}